// round 5
// baseline (speedup 1.0000x reference)
#include <cuda_runtime.h>
#include <cuda_bf16.h>
#include <cstdint>
#include <cstddef>

typedef __nv_bfloat16 bf16;

#define NN 8192
#define STAGE_BYTES 49152u
#define SMEM_BYTES (3 * 49152)

// ---------------- device scratch (no allocs allowed; zero-init at load) ----
__device__ __align__(1024) bf16 g_adj_hi[(size_t)NN * NN];
__device__ __align__(1024) bf16 g_adj_lo[(size_t)NN * NN];
__device__ __align__(1024) bf16 g_ht_hi[256 * NN];           // transposed features [F][NN]
__device__ __align__(1024) bf16 g_ht_lo[256 * NN];
__device__ __align__(1024) bf16 g_catA_hi[(size_t)NN * 512]; // layer1 concat [h|support]
__device__ __align__(1024) bf16 g_catA_lo[(size_t)NN * 512];
__device__ __align__(1024) bf16 g_catB_hi[(size_t)NN * 256]; // layers 2-4 concat
__device__ __align__(1024) bf16 g_catB_lo[(size_t)NN * 256];
__device__ __align__(1024) bf16 g_wt_hi[163840];             // W^T; layer4 padded to 128 rows
__device__ __align__(1024) bf16 g_wt_lo[163840];

// ---------------- helpers ----------------
__device__ __forceinline__ uint32_t s2u(const void* p) {
    uint32_t a;
    asm("{ .reg .u64 t; cvta.to.shared.u64 t, %1; cvt.u32.u64 %0, t; }" : "=r"(a) : "l"(p));
    return a;
}

#define CP16(dst_u32, src_ptr) \
    asm volatile("cp.async.cg.shared.global [%0], [%1], 16;" :: "r"(dst_u32), "l"(src_ptr) : "memory")

__device__ __forceinline__ void ldsm4(uint32_t a[4], uint32_t addr) {
    asm volatile("ldmatrix.sync.aligned.m8n8.x4.shared.b16 {%0,%1,%2,%3}, [%4];"
                 : "=r"(a[0]), "=r"(a[1]), "=r"(a[2]), "=r"(a[3]) : "r"(addr));
}

__device__ __forceinline__ void mma16816(float c[4], const uint32_t a[4], const uint32_t b[2]) {
    asm volatile(
        "mma.sync.aligned.m16n8k16.row.col.f32.bf16.bf16.f32 "
        "{%0,%1,%2,%3}, {%4,%5,%6,%7}, {%8,%9}, {%0,%1,%2,%3};"
        : "+f"(c[0]), "+f"(c[1]), "+f"(c[2]), "+f"(c[3])
        : "r"(a[0]), "r"(a[1]), "r"(a[2]), "r"(a[3]), "r"(b[0]), "r"(b[1]));
}

__device__ __forceinline__ void split2(float v, bf16& h, bf16& l) {
    h = __float2bfloat16(v);
    l = __float2bfloat16(v - __bfloat162float(h));
}

// ---------------- prep kernels ----------------
__global__ void k_split(const float4* __restrict__ src, bf16* __restrict__ hi,
                        bf16* __restrict__ lo, size_t n4) {
    size_t i = (size_t)blockIdx.x * blockDim.x + threadIdx.x;
    size_t stride = (size_t)gridDim.x * blockDim.x;
    for (; i < n4; i += stride) {
        float4 v = src[i];
        bf16 h0, h1, h2, h3, l0, l1, l2, l3;
        split2(v.x, h0, l0); split2(v.y, h1, l1);
        split2(v.z, h2, l2); split2(v.w, h3, l3);
        __nv_bfloat162* H = (__nv_bfloat162*)hi;
        __nv_bfloat162* L = (__nv_bfloat162*)lo;
        H[2 * i]     = __halves2bfloat162(h0, h1);
        H[2 * i + 1] = __halves2bfloat162(h2, h3);
        L[2 * i]     = __halves2bfloat162(l0, l1);
        L[2 * i + 1] = __halves2bfloat162(l2, l3);
    }
}

// x [8192,256] fp32 -> catA cols [0,256) row-major split, ld=512
__global__ void k_xcat(const float4* __restrict__ x4, bf16* __restrict__ hi,
                       bf16* __restrict__ lo) {
    int idx = blockIdx.x * blockDim.x + threadIdx.x;  // 8192*64
    int row = idx >> 6, c4 = idx & 63;
    float4 v = x4[idx];
    size_t base = (size_t)row * 512 + c4 * 4;
    bf16 h0, h1, h2, h3, l0, l1, l2, l3;
    split2(v.x, h0, l0); split2(v.y, h1, l1);
    split2(v.z, h2, l2); split2(v.w, h3, l3);
    __nv_bfloat162* H = (__nv_bfloat162*)(hi + base);
    __nv_bfloat162* L = (__nv_bfloat162*)(lo + base);
    H[0] = __halves2bfloat162(h0, h1); H[1] = __halves2bfloat162(h2, h3);
    L[0] = __halves2bfloat162(l0, l1); L[1] = __halves2bfloat162(l2, l3);
}

// transpose + split: src [R, C] fp32 -> dst[c][r] split bf16 (dst ld = R)
__global__ void k_tsplit(const float* __restrict__ src, int R, int C,
                         bf16* __restrict__ dhi, bf16* __restrict__ dlo) {
    __shared__ float t[32][33];
    int bx = blockIdx.x * 32;   // col base (over C)
    int by = blockIdx.y * 32;   // row base (over R)
    int tx = threadIdx.x, ty = threadIdx.y;
    #pragma unroll
    for (int i = 0; i < 4; i++)
        t[ty + 8 * i][tx] = src[(size_t)(by + ty + 8 * i) * C + bx + tx];
    __syncthreads();
    #pragma unroll
    for (int i = 0; i < 4; i++) {
        int c = bx + ty + 8 * i;
        float v = t[tx][ty + 8 * i];
        bf16 h, l; split2(v, h, l);
        dhi[(size_t)c * R + by + tx] = h;
        dlo[(size_t)c * R + by + tx] = l;
    }
}

// ---------------- split-bf16 3-product HMMA GEMM ----------------
// C[m0+64, n0+128] = sum_k (Ah+Al)[m,k]*(Bh+Bl)[n,k]   (Al*Bl dropped)
// A row-major [M][K] (k-contig), B row-major [N][K] (k-contig = col-major B)
// mode 0: write split bf16 -> orm (row-major, ld_rm)
// mode 1: +bias, relu; write split -> orm AND transposed -> ot (ld NN)
// mode 2: +bias; write fp32 -> of (ld Ncols), cols < Ncols only
// Stage layout (48KB): Ah[64][128B] @0, Al @8192, Bh[128][128B] @16384, Bl @32768
__device__ __forceinline__ void load_stage(
    uint32_t sb, int stage, int kc,
    const bf16* Ah, const bf16* Al, int lda,
    const bf16* Bh, const bf16* Bl, int ldb,
    int m0, int n0, int tid) {
    uint32_t st = sb + (uint32_t)stage * STAGE_BYTES;
    #pragma unroll
    for (int i = 0; i < 4; ++i) {
        int g = tid + (i << 8);
        int sub = g >> 9;          // 0=hi, 1=lo
        int idx = g & 511;
        int row = idx >> 3;
        int cb = (idx & 7) << 4;   // byte col 0..112
        uint32_t dst = st + (uint32_t)(sub * 8192) + (uint32_t)(row * 128)
                     + (uint32_t)(cb ^ ((row & 7) << 4));
        const bf16* srcb = sub ? Al : Ah;
        CP16(dst, (const char*)(srcb + (size_t)(m0 + row) * lda + kc) + cb);
    }
    #pragma unroll
    for (int i = 0; i < 8; ++i) {
        int g = tid + (i << 8);
        int sub = g >> 10;
        int idx = g & 1023;
        int row = idx >> 3;
        int cb = (idx & 7) << 4;
        uint32_t dst = st + 16384u + (uint32_t)(sub * 16384) + (uint32_t)(row * 128)
                     + (uint32_t)(cb ^ ((row & 7) << 4));
        const bf16* srcb = sub ? Bl : Bh;
        CP16(dst, (const char*)(srcb + (size_t)(n0 + row) * ldb + kc) + cb);
    }
}

__global__ void __launch_bounds__(256, 1)
k_gemm(const bf16* __restrict__ Ah, const bf16* __restrict__ Al, int lda,
       const bf16* __restrict__ Bh, const bf16* __restrict__ Bl, int ldb,
       int K, int mode, int Ncols, const float* __restrict__ bias,
       bf16* __restrict__ orm_hi, bf16* __restrict__ orm_lo, int ld_rm,
       bf16* __restrict__ ot_hi, bf16* __restrict__ ot_lo,
       float* __restrict__ of) {
    extern __shared__ char smem[];
    const int tid = threadIdx.x;
    const uint32_t sb = s2u(smem);
    const int m0 = (int)blockIdx.y * 64;
    const int n0 = (int)blockIdx.x * 128;
    const int lane = tid & 31, wid = tid >> 5;
    const int wm = wid >> 2, wn = wid & 3;          // 2 x 4 warp grid
    const int lg = lane >> 3, lr = lane & 7;

    // ldmatrix lane roles
    const int arow = wm * 32 + (lg & 1) * 8 + lr;   // + mi*16
    const uint32_t acol = (uint32_t)((lg >> 1) * 16);
    const uint32_t axr = (uint32_t)((arow & 7) << 4);
    const int brow = wn * 32 + (lg >> 1) * 8 + lr;  // + nh*16
    const uint32_t bcol = (uint32_t)((lg & 1) * 16);
    const uint32_t bxr = (uint32_t)((brow & 7) << 4);

    float acc[2][4][4] = {};
    const int C = K >> 6;

    // prologue: stages 0,1
    #pragma unroll
    for (int c = 0; c < 2; ++c) {
        load_stage(sb, c, c << 6, Ah, Al, lda, Bh, Bl, ldb, m0, n0, tid);
        asm volatile("cp.async.commit_group;" ::: "memory");
    }

    for (int c = 0; c < C; ++c) {
        asm volatile("cp.async.wait_group 1;" ::: "memory");
        __syncthreads();
        int nc = c + 2;
        if (nc < C)
            load_stage(sb, nc % 3, nc << 6, Ah, Al, lda, Bh, Bl, ldb, m0, n0, tid);
        asm volatile("cp.async.commit_group;" ::: "memory");

        uint32_t st = sb + (uint32_t)((c % 3) * STAGE_BYTES);
        uint32_t aB = st + (uint32_t)(arow * 128);
        uint32_t bB = st + 16384u + (uint32_t)(brow * 128);
        #pragma unroll
        for (int kq = 0; kq < 4; ++kq) {
            uint32_t ac = ((uint32_t)(kq * 32) + acol) ^ axr;
            uint32_t bc = ((uint32_t)(kq * 32) + bcol) ^ bxr;
            uint32_t ah[2][4], al[2][4], bh[2][4], bl[2][4];
            ldsm4(ah[0], aB + ac);
            ldsm4(ah[1], aB + 2048u + ac);             // +16 rows
            ldsm4(al[0], aB + 8192u + ac);
            ldsm4(al[1], aB + 8192u + 2048u + ac);
            ldsm4(bh[0], bB + bc);
            ldsm4(bh[1], bB + 2048u + bc);             // +16 n-rows
            ldsm4(bl[0], bB + 16384u + bc);
            ldsm4(bl[1], bB + 16384u + 2048u + bc);
            #pragma unroll
            for (int mi = 0; mi < 2; ++mi)
                #pragma unroll
                for (int ni = 0; ni < 4; ++ni) {
                    const uint32_t* bph = &bh[ni >> 1][(ni & 1) * 2];
                    const uint32_t* bpl = &bl[ni >> 1][(ni & 1) * 2];
                    mma16816(acc[mi][ni], ah[mi], bph);
                    mma16816(acc[mi][ni], ah[mi], bpl);
                    mma16816(acc[mi][ni], al[mi], bph);
                }
        }
    }

    // ---------------- epilogue ----------------
    #pragma unroll
    for (int mi = 0; mi < 2; ++mi) {
        int r0 = m0 + wm * 32 + mi * 16 + (lane >> 2);
        #pragma unroll
        for (int ni = 0; ni < 4; ++ni) {
            int c = n0 + wn * 32 + ni * 8 + ((lane & 3) << 1);
            float v0 = acc[mi][ni][0], v1 = acc[mi][ni][1];
            float v2 = acc[mi][ni][2], v3 = acc[mi][ni][3];
            if (mode == 2) {
                if (c < Ncols) {
                    float b0v = bias[c], b1v = bias[c + 1];
                    of[(size_t)r0 * Ncols + c]           = v0 + b0v;
                    of[(size_t)r0 * Ncols + c + 1]       = v1 + b1v;
                    of[(size_t)(r0 + 8) * Ncols + c]     = v2 + b0v;
                    of[(size_t)(r0 + 8) * Ncols + c + 1] = v3 + b1v;
                }
            } else {
                if (mode == 1) {
                    float b0v = bias[c], b1v = bias[c + 1];
                    v0 = fmaxf(v0 + b0v, 0.f); v1 = fmaxf(v1 + b1v, 0.f);
                    v2 = fmaxf(v2 + b0v, 0.f); v3 = fmaxf(v3 + b1v, 0.f);
                }
                bf16 h0, l0, h1, l1, h2, l2, h3, l3;
                split2(v0, h0, l0); split2(v1, h1, l1);
                split2(v2, h2, l2); split2(v3, h3, l3);
                *(__nv_bfloat162*)(orm_hi + (size_t)r0 * ld_rm + c) = __halves2bfloat162(h0, h1);
                *(__nv_bfloat162*)(orm_lo + (size_t)r0 * ld_rm + c) = __halves2bfloat162(l0, l1);
                *(__nv_bfloat162*)(orm_hi + (size_t)(r0 + 8) * ld_rm + c) = __halves2bfloat162(h2, h3);
                *(__nv_bfloat162*)(orm_lo + (size_t)(r0 + 8) * ld_rm + c) = __halves2bfloat162(l2, l3);
                if (mode == 1) {
                    ot_hi[(size_t)c * NN + r0] = h0;       ot_lo[(size_t)c * NN + r0] = l0;
                    ot_hi[(size_t)(c + 1) * NN + r0] = h1; ot_lo[(size_t)(c + 1) * NN + r0] = l1;
                    ot_hi[(size_t)c * NN + r0 + 8] = h2;   ot_lo[(size_t)c * NN + r0 + 8] = l2;
                    ot_hi[(size_t)(c + 1) * NN + r0 + 8] = h3;
                    ot_lo[(size_t)(c + 1) * NN + r0 + 8] = l3;
                }
            }
        }
    }
}

// ---------------- host ----------------
static void* symaddr(const void* sym) {
    void* p = nullptr;
    cudaGetSymbolAddress(&p, sym);
    return p;
}

extern "C" void kernel_launch(void* const* d_in, const int* in_sizes, int n_in,
                              void* d_out, int out_size) {
    (void)in_sizes; (void)n_in; (void)out_size;
    const float* x   = (const float*)d_in[0];
    const float* adj = (const float*)d_in[1];
    const float* W1  = (const float*)d_in[2];
    const float* b1  = (const float*)d_in[3];
    const float* W2  = (const float*)d_in[4];
    const float* b2  = (const float*)d_in[5];
    const float* W3  = (const float*)d_in[6];
    const float* b3  = (const float*)d_in[7];
    const float* W4  = (const float*)d_in[8];
    const float* b4  = (const float*)d_in[9];

    bf16* adj_hi  = (bf16*)symaddr(g_adj_hi);
    bf16* adj_lo  = (bf16*)symaddr(g_adj_lo);
    bf16* ht_hi   = (bf16*)symaddr(g_ht_hi);
    bf16* ht_lo   = (bf16*)symaddr(g_ht_lo);
    bf16* catA_hi = (bf16*)symaddr(g_catA_hi);
    bf16* catA_lo = (bf16*)symaddr(g_catA_lo);
    bf16* catB_hi = (bf16*)symaddr(g_catB_hi);
    bf16* catB_lo = (bf16*)symaddr(g_catB_lo);
    bf16* wt_hi   = (bf16*)symaddr(g_wt_hi);
    bf16* wt_lo   = (bf16*)symaddr(g_wt_lo);

    cudaFuncSetAttribute(k_gemm, cudaFuncAttributeMaxDynamicSharedMemorySize, SMEM_BYTES);

    // ---- prep ----
    k_split<<<4096, 256>>>((const float4*)adj, adj_hi, adj_lo, (size_t)NN * NN / 4);
    k_xcat<<<2048, 256>>>((const float4*)x, catA_hi, catA_lo);
    k_tsplit<<<dim3(8, 256), dim3(32, 8)>>>(x, NN, 256, ht_hi, ht_lo);          // x^T
    k_tsplit<<<dim3(4, 16),  dim3(32, 8)>>>(W1, 512, 128, wt_hi,          wt_lo);
    k_tsplit<<<dim3(4, 8),   dim3(32, 8)>>>(W2, 256, 128, wt_hi + 65536,  wt_lo + 65536);
    k_tsplit<<<dim3(4, 8),   dim3(32, 8)>>>(W3, 256, 128, wt_hi + 98304,  wt_lo + 98304);
    k_tsplit<<<dim3(2, 8),   dim3(32, 8)>>>(W4, 256, 64,  wt_hi + 131072, wt_lo + 131072);
    // wt layer4 rows 64..127 remain zero (device globals are zero-initialized)

    // ---- layer 1 ----
    k_gemm<<<dim3(2, 128), 256, SMEM_BYTES>>>(adj_hi, adj_lo, NN, ht_hi, ht_lo, NN,
        NN, 0, 256, nullptr, catA_hi + 256, catA_lo + 256, 512, nullptr, nullptr, nullptr);
    k_gemm<<<dim3(1, 128), 256, SMEM_BYTES>>>(catA_hi, catA_lo, 512, wt_hi, wt_lo, 512,
        512, 1, 128, b1, catB_hi, catB_lo, 256, ht_hi, ht_lo, nullptr);

    // ---- layer 2 ----
    k_gemm<<<dim3(1, 128), 256, SMEM_BYTES>>>(adj_hi, adj_lo, NN, ht_hi, ht_lo, NN,
        NN, 0, 128, nullptr, catB_hi + 128, catB_lo + 128, 256, nullptr, nullptr, nullptr);
    k_gemm<<<dim3(1, 128), 256, SMEM_BYTES>>>(catB_hi, catB_lo, 256,
        wt_hi + 65536, wt_lo + 65536, 256,
        256, 1, 128, b2, catB_hi, catB_lo, 256, ht_hi, ht_lo, nullptr);

    // ---- layer 3 ----
    k_gemm<<<dim3(1, 128), 256, SMEM_BYTES>>>(adj_hi, adj_lo, NN, ht_hi, ht_lo, NN,
        NN, 0, 128, nullptr, catB_hi + 128, catB_lo + 128, 256, nullptr, nullptr, nullptr);
    k_gemm<<<dim3(1, 128), 256, SMEM_BYTES>>>(catB_hi, catB_lo, 256,
        wt_hi + 98304, wt_lo + 98304, 256,
        256, 1, 128, b3, catB_hi, catB_lo, 256, ht_hi, ht_lo, nullptr);

    // ---- layer 4 (fp32 output, N=64 padded to 128 in B) ----
    k_gemm<<<dim3(1, 128), 256, SMEM_BYTES>>>(adj_hi, adj_lo, NN, ht_hi, ht_lo, NN,
        NN, 0, 128, nullptr, catB_hi + 128, catB_lo + 128, 256, nullptr, nullptr, nullptr);
    k_gemm<<<dim3(1, 128), 256, SMEM_BYTES>>>(catB_hi, catB_lo, 256,
        wt_hi + 131072, wt_lo + 131072, 256,
        256, 2, 64, b4, nullptr, nullptr, 0, nullptr, nullptr, (float*)d_out);
}